// round 5
// baseline (speedup 1.0000x reference)
#include <cuda_runtime.h>
#include <math.h>

#define BB 2
#define NN 8192
#define DIMM 512
#define GH 6
#define DH 64
#define NBF 256
#define NWIN 32
#define WINSZ 256
#define BHG (BB*GH)      // 12
#define BHL 4            // B * LOCAL_HEADS
#define NSPLIT 16

// ---------------- scratch (device globals: alloc-free) ----------------
__device__ float g_q[BB*NN*DIMM];
__device__ float g_k[BB*NN*DIMM];
__device__ float g_v[BB*NN*DIMM];
__device__ float g_qp[BHG*NN*NBF];
__device__ float g_kp[BHG*NN*NBF];
__device__ float g_kmaxp[BHG*64];
__device__ float g_kmax[BHG];
__device__ float g_part[BHG*NSPLIT*256*65];
__device__ float g_ctx[BHG*256*68];
__device__ float g_dinv[BHG*NN];
__device__ float g_att[BB*NN*DIMM];
__device__ float g_sc[(size_t)BHL*NWIN*WINSZ*768];
__device__ float g_rq[BHL*NN*DH];
__device__ float g_rk[BHL*NN*DH];

// ---------------- generic 128x128x16 SGEMM, row-major, optional bias ----------------
__global__ void __launch_bounds__(256) sgemm128(
    const float* __restrict__ A, const float* __restrict__ Bm,
    const float* __restrict__ bias, float* __restrict__ C,
    int M, int Nn, int K)
{
    __shared__ __align__(16) float As[16][128];
    __shared__ __align__(16) float Bs[16][128];
    int bx = blockIdx.x, by = blockIdx.y;
    int tid = threadIdx.x;
    int tx = tid % 16, ty = tid / 16;
    float acc[8][8] = {};

    int a_row  = tid >> 2;         // 0..63
    int a_col4 = (tid & 3) * 4;    // 0,4,8,12
    int b_row  = tid >> 5;         // 0..7
    int b_col4 = (tid & 31) * 4;   // 0..124

    const float* Aptr = A + (size_t)(by * 128) * K;
    const float* Bptr = Bm + bx * 128;

    for (int k0 = 0; k0 < K; k0 += 16) {
#pragma unroll
        for (int i = 0; i < 2; i++) {
            int r = a_row + i * 64;
            float4 va = *(const float4*)(Aptr + (size_t)r * K + k0 + a_col4);
            As[a_col4+0][r] = va.x; As[a_col4+1][r] = va.y;
            As[a_col4+2][r] = va.z; As[a_col4+3][r] = va.w;
        }
#pragma unroll
        for (int i = 0; i < 2; i++) {
            int r = b_row + i * 8;
            float4 vb = *(const float4*)(Bptr + (size_t)(k0 + r) * Nn + b_col4);
            *(float4*)&Bs[r][b_col4] = vb;
        }
        __syncthreads();
#pragma unroll
        for (int kk = 0; kk < 16; kk++) {
            float4 a0 = *(const float4*)&As[kk][ty*8];
            float4 a1 = *(const float4*)&As[kk][ty*8+4];
            float4 b0 = *(const float4*)&Bs[kk][tx*8];
            float4 b1 = *(const float4*)&Bs[kk][tx*8+4];
            float af[8] = {a0.x,a0.y,a0.z,a0.w,a1.x,a1.y,a1.z,a1.w};
            float bf[8] = {b0.x,b0.y,b0.z,b0.w,b1.x,b1.y,b1.z,b1.w};
#pragma unroll
            for (int i = 0; i < 8; i++)
#pragma unroll
                for (int j = 0; j < 8; j++)
                    acc[i][j] += af[i] * bf[j];
        }
        __syncthreads();
    }
#pragma unroll
    for (int i = 0; i < 8; i++) {
        int r = by * 128 + ty * 8 + i;
#pragma unroll
        for (int j = 0; j < 8; j += 4) {
            int c = bx * 128 + tx * 8 + j;
            float4 v;
            v.x = acc[i][j]; v.y = acc[i][j+1]; v.z = acc[i][j+2]; v.w = acc[i][j+3];
            if (bias) { v.x += bias[c]; v.y += bias[c+1]; v.z += bias[c+2]; v.w += bias[c+3]; }
            *(float4*)(C + (size_t)r * Nn + c) = v;
        }
    }
}

// ---------------- dd = (data*norm) @ proj^T  per global head ----------------
__global__ void __launch_bounds__(256) dd_kernel(
    const float* __restrict__ data, const float* __restrict__ proj, float* __restrict__ dd)
{
    __shared__ __align__(16) float As[64][68];
    __shared__ __align__(16) float Bs[64][68];
    int bh = blockIdx.z; int b = bh / GH, h = bh % GH;
    int n0 = blockIdx.y * 64, j0 = blockIdx.x * 64;
    int tid = threadIdx.x;
    int lr = tid >> 2, lc4 = (tid & 3) * 4;
    const float* db = data + ((size_t)b * NN + n0) * DIMM + h * 64;
    const float* pb = proj + (size_t)j0 * 64;
    const float NORM = 0.35355339059327373f;
#pragma unroll
    for (int i = 0; i < 4; i++) {
        int c = lc4 + i * 16;
        float4 va = *(const float4*)(db + (size_t)lr * DIMM + c);
        As[c+0][lr] = va.x * NORM; As[c+1][lr] = va.y * NORM;
        As[c+2][lr] = va.z * NORM; As[c+3][lr] = va.w * NORM;
        float4 vb = *(const float4*)(pb + (size_t)lr * 64 + c);
        Bs[c+0][lr] = vb.x; Bs[c+1][lr] = vb.y; Bs[c+2][lr] = vb.z; Bs[c+3][lr] = vb.w;
    }
    __syncthreads();
    int tx = tid & 15, ty = tid >> 4;
    float acc[4][4] = {};
#pragma unroll
    for (int kk = 0; kk < 64; kk++) {
        float4 a  = *(const float4*)&As[kk][ty*4];
        float4 bv = *(const float4*)&Bs[kk][tx*4];
        float av[4] = {a.x,a.y,a.z,a.w}, bb[4] = {bv.x,bv.y,bv.z,bv.w};
#pragma unroll
        for (int i = 0; i < 4; i++)
#pragma unroll
            for (int j = 0; j < 4; j++) acc[i][j] += av[i] * bb[j];
    }
    float* ob = dd + ((size_t)bh * NN + n0) * NBF + j0;
#pragma unroll
    for (int i = 0; i < 4; i++) {
        float4 o = {acc[i][0], acc[i][1], acc[i][2], acc[i][3]};
        *(float4*)(ob + (size_t)(ty*4+i) * NBF + tx*4) = o;
    }
}

// ---------------- k max reduction (two stage) ----------------
__global__ void kmax_part_kernel(const float* __restrict__ kdd, float* __restrict__ kpart)
{
    int bh = blockIdx.y, s = blockIdx.x;
    const int CH = NN * NBF / 64;
    const float* p = kdd + (size_t)bh * NN * NBF + (size_t)s * CH;
    float m = -1e30f;
    for (int i = threadIdx.x; i < CH; i += 256) m = fmaxf(m, p[i]);
#pragma unroll
    for (int o = 16; o > 0; o >>= 1) m = fmaxf(m, __shfl_xor_sync(0xffffffffu, m, o));
    __shared__ float red[8];
    if ((threadIdx.x & 31) == 0) red[threadIdx.x >> 5] = m;
    __syncthreads();
    if (threadIdx.x == 0) {
        float z = red[0];
#pragma unroll
        for (int i = 1; i < 8; i++) z = fmaxf(z, red[i]);
        kpart[bh * 64 + s] = z;
    }
}
__global__ void kmax_final_kernel(const float* __restrict__ kpart, float* __restrict__ kmax)
{
    int bh = blockIdx.x;
    float m = kpart[bh * 64 + threadIdx.x];
#pragma unroll
    for (int o = 16; o > 0; o >>= 1) m = fmaxf(m, __shfl_xor_sync(0xffffffffu, m, o));
    __shared__ float red[2];
    if ((threadIdx.x & 31) == 0) red[threadIdx.x >> 5] = m;
    __syncthreads();
    if (threadIdx.x == 0) kmax[bh] = fmaxf(red[0], red[1]);
}

// ---------------- qp/kp = ratio*(exp(dd - diag - m) + eps) ----------------
__global__ void qexp_kernel(const float* __restrict__ qdata, float* __restrict__ qp)
{
    int row = blockIdx.x * 8 + (threadIdx.x >> 5);
    int lane = threadIdx.x & 31;
    int bh = row >> 13, n = row & (NN - 1);
    int b = bh / GH, h = bh % GH;
    const float* dr = qdata + ((size_t)b * NN + n) * DIMM + h * 64;
    float2 v2 = *(const float2*)(dr + lane * 2);
    float sq = v2.x * v2.x + v2.y * v2.y;
#pragma unroll
    for (int o = 16; o > 0; o >>= 1) sq += __shfl_xor_sync(0xffffffffu, sq, o);
    float diag = sq * 0.0625f;
    float* pr = qp + (size_t)row * NBF;
    float vals[8]; float m = -1e30f;
#pragma unroll
    for (int i = 0; i < 8; i++) { vals[i] = pr[lane + i * 32]; m = fmaxf(m, vals[i]); }
#pragma unroll
    for (int o = 16; o > 0; o >>= 1) m = fmaxf(m, __shfl_xor_sync(0xffffffffu, m, o));
#pragma unroll
    for (int i = 0; i < 8; i++)
        pr[lane + i * 32] = 0.0625f * (expf(vals[i] - diag - m) + 1e-4f);
}
__global__ void kexp_kernel(const float* __restrict__ kdata, const float* __restrict__ kmax,
                            float* __restrict__ kp)
{
    int row = blockIdx.x * 8 + (threadIdx.x >> 5);
    int lane = threadIdx.x & 31;
    int bh = row >> 13, n = row & (NN - 1);
    int b = bh / GH, h = bh % GH;
    const float* dr = kdata + ((size_t)b * NN + n) * DIMM + h * 64;
    float2 v2 = *(const float2*)(dr + lane * 2);
    float sq = v2.x * v2.x + v2.y * v2.y;
#pragma unroll
    for (int o = 16; o > 0; o >>= 1) sq += __shfl_xor_sync(0xffffffffu, sq, o);
    float diag = sq * 0.0625f;
    float m = kmax[bh];
    float* pr = kp + (size_t)row * NBF;
#pragma unroll
    for (int i = 0; i < 8; i++)
        pr[lane + i * 32] = 0.0625f * (expf(pr[lane + i * 32] - diag - m) + 1e-4f);
}

// ---------------- ctx[j][d] = sum_n kp[n,j]*v[n,d]  (split-K, col 64 = k_sum) ----------------
__global__ void __launch_bounds__(256) ctx_partial_kernel(
    const float* __restrict__ kp, const float* __restrict__ v, float* __restrict__ part)
{
    int bh = blockIdx.x, sp = blockIdx.y;
    int b = bh / GH, h = bh % GH;
    int j = threadIdx.x;
    float acc[65];
#pragma unroll
    for (int d = 0; d < 65; d++) acc[d] = 0.f;
    __shared__ __align__(16) float vs[16][68];
    const float* kpb = kp + ((size_t)bh * NN + sp * 512) * NBF + j;
    const float* vb = v + ((size_t)b * NN + sp * 512) * DIMM + h * 64;
    for (int n0 = 0; n0 < 512; n0 += 16) {
        __syncthreads();
        int r = threadIdx.x >> 4;
        int c = (threadIdx.x & 15) * 4;
        float4 vv = *(const float4*)(vb + (size_t)(n0 + r) * DIMM + c);
        *(float4*)&vs[r][c] = vv;
        if ((threadIdx.x & 15) == 0) vs[r][64] = 1.f;
        __syncthreads();
#pragma unroll 2
        for (int nn = 0; nn < 16; nn++) {
            float p = kpb[(size_t)(n0 + nn) * NBF];
#pragma unroll
            for (int d = 0; d < 65; d++) acc[d] += p * vs[nn][d];
        }
    }
    float* o = part + (((size_t)bh * NSPLIT + sp) * 256 + j) * 65;
#pragma unroll
    for (int d = 0; d < 65; d++) o[d] = acc[d];
}
__global__ void ctx_reduce_kernel(const float* __restrict__ part, float* __restrict__ ctx)
{
    int idx = blockIdx.x * 256 + threadIdx.x;
    if (idx >= BHG * 256 * 65) return;
    int bh = idx / (256 * 65); int rem = idx - bh * 256 * 65;
    int j = rem / 65, d = rem % 65;
    float s = 0.f;
#pragma unroll
    for (int sp = 0; sp < NSPLIT; sp++)
        s += part[(((size_t)bh * NSPLIT + sp) * 256 + j) * 65 + d];
    ctx[((size_t)bh * 256 + j) * 68 + d] = s;
}

// ---------------- d_inv = 1 / (qp . k_sum) ----------------
__global__ void denom_kernel(const float* __restrict__ qp, const float* __restrict__ ctx,
                             float* __restrict__ dinv)
{
    int row = blockIdx.x * 8 + (threadIdx.x >> 5);
    int lane = threadIdx.x & 31;
    int bh = row >> 13;
    const float* q = qp + (size_t)row * NBF;
    const float* ks = ctx + (size_t)bh * 256 * 68 + 64;
    float s = 0.f;
#pragma unroll
    for (int i = 0; i < 8; i++) s += q[lane + i * 32] * ks[(size_t)(lane + i * 32) * 68];
#pragma unroll
    for (int o = 16; o > 0; o >>= 1) s += __shfl_xor_sync(0xffffffffu, s, o);
    if (lane == 0) dinv[row] = 1.f / s;
}

// ---------------- out_g = (qp @ ctx) * d_inv -> att ----------------
__global__ void __launch_bounds__(256) outg_kernel(
    const float* __restrict__ qp, const float* __restrict__ ctx,
    const float* __restrict__ dinv, float* __restrict__ att)
{
    __shared__ __align__(16) float Qs[32][68];
    __shared__ __align__(16) float Cs[32][68];
    int bh = blockIdx.y; int b = bh / GH, h = bh % GH;
    int n0 = blockIdx.x * 64;
    int tid = threadIdx.x;
    int tx = tid & 15, ty = tid >> 4;
    float acc[4][4] = {};
    const float* qbase = qp + ((size_t)bh * NN + n0) * NBF;
    const float* cbase = ctx + (size_t)bh * 256 * 68;
    for (int k0 = 0; k0 < 256; k0 += 32) {
        int r = tid >> 3, c4 = (tid & 7) * 4;
#pragma unroll
        for (int i = 0; i < 2; i++) {
            float4 v = *(const float4*)(qbase + (size_t)(r + i * 32) * NBF + k0 + c4);
            Qs[c4+0][r+i*32] = v.x; Qs[c4+1][r+i*32] = v.y;
            Qs[c4+2][r+i*32] = v.z; Qs[c4+3][r+i*32] = v.w;
        }
        int cr = tid >> 4, cc4 = (tid & 15) * 4;
#pragma unroll
        for (int i = 0; i < 2; i++) {
            float4 v = *(const float4*)(cbase + (size_t)(k0 + cr + i * 16) * 68 + cc4);
            *(float4*)&Cs[cr + i * 16][cc4] = v;
        }
        __syncthreads();
#pragma unroll
        for (int kk = 0; kk < 32; kk++) {
            float4 a  = *(const float4*)&Qs[kk][ty*4];
            float4 bv = *(const float4*)&Cs[kk][tx*4];
            float av[4] = {a.x,a.y,a.z,a.w}, bb[4] = {bv.x,bv.y,bv.z,bv.w};
#pragma unroll
            for (int i = 0; i < 4; i++)
#pragma unroll
                for (int j = 0; j < 4; j++) acc[i][j] += av[i] * bb[j];
        }
        __syncthreads();
    }
#pragma unroll
    for (int i = 0; i < 4; i++) {
        int n = n0 + ty * 4 + i;
        float di = dinv[(size_t)bh * NN + n];
        float4 o = {acc[i][0]*di, acc[i][1]*di, acc[i][2]*di, acc[i][3]*di};
        *(float4*)(att + ((size_t)b * NN + n) * DIMM + h * 64 + tx * 4) = o;
    }
}

// ---------------- RoPE for local heads ----------------
__global__ void rope_kernel(const float* __restrict__ q, const float* __restrict__ k,
                            float* __restrict__ rq, float* __restrict__ rk)
{
    int idx = blockIdx.x * blockDim.x + threadIdx.x; // over BHL*NN*32
    int i = idx & 31;
    int n = (idx >> 5) & (NN - 1);
    int bh = idx >> 18;
    int b = bh >> 1, lh = bh & 1;
    float invf = (float)exp(-(double)(2 * i) / 64.0 * 9.210340371976184);
    float ang = (float)n * invf;
    float s, c;
    sincosf(ang, &s, &c);
    size_t base = ((size_t)b * NN + n) * DIMM + (GH + lh) * 64;
    float q1 = q[base + i], q2 = q[base + 32 + i];
    float k1 = k[base + i], k2 = k[base + 32 + i];
    size_t ob = ((size_t)bh * NN + n) * DH;
    rq[ob + i]      = q1 * c - q2 * s;
    rq[ob + 32 + i] = q2 * c + q1 * s;
    rk[ob + i]      = k1 * c - k2 * s;
    rk[ob + 32 + i] = k2 * c + k1 * s;
}

// ---------------- local scores = 0.125 * bq @ bk3^T with masking ----------------
__global__ void __launch_bounds__(256) lscore_kernel(
    const float* __restrict__ rq, const float* __restrict__ rk, float* __restrict__ sc)
{
    __shared__ __align__(16) float Qs[64][68];
    __shared__ __align__(16) float Ks[64][68];
    int bw = blockIdx.z; int bh = bw >> 5; int w = bw & 31;
    int m0 = blockIdx.y * 64, c0 = blockIdx.x * 64;
    int tid = threadIdx.x;
    int lr = tid >> 2, lc4 = (tid & 3) * 4;
    const float* qb = rq + ((size_t)bh * NN + w * WINSZ + m0) * DH;
    const float* kb = rk + (size_t)bh * NN * DH;
    int knr = (w - 1) * WINSZ + c0 + lr;
    bool kvalid = (unsigned)knr < (unsigned)NN;
#pragma unroll
    for (int i = 0; i < 4; i++) {
        int c = lc4 + i * 16;
        float4 va = *(const float4*)(qb + (size_t)lr * DH + c);
        Qs[c+0][lr] = va.x; Qs[c+1][lr] = va.y; Qs[c+2][lr] = va.z; Qs[c+3][lr] = va.w;
        float4 vk = make_float4(0.f, 0.f, 0.f, 0.f);
        if (kvalid) vk = *(const float4*)(kb + (size_t)knr * DH + c);
        Ks[c+0][lr] = vk.x; Ks[c+1][lr] = vk.y; Ks[c+2][lr] = vk.z; Ks[c+3][lr] = vk.w;
    }
    __syncthreads();
    int tx = tid & 15, ty = tid >> 4;
    float acc[4][4] = {};
#pragma unroll
    for (int kk = 0; kk < 64; kk++) {
        float4 a  = *(const float4*)&Qs[kk][ty*4];
        float4 bv = *(const float4*)&Ks[kk][tx*4];
        float av[4] = {a.x,a.y,a.z,a.w}, bb[4] = {bv.x,bv.y,bv.z,bv.w};
#pragma unroll
        for (int i = 0; i < 4; i++)
#pragma unroll
            for (int j = 0; j < 4; j++) acc[i][j] += av[i] * bb[j];
    }
    int kn0 = (w - 1) * WINSZ + c0 + tx * 4;
    bool valid = (unsigned)kn0 < (unsigned)NN;
    float* ob = sc + ((size_t)bw * WINSZ + m0) * 768 + c0;
#pragma unroll
    for (int i = 0; i < 4; i++) {
        float4 o;
        o.x = valid ? acc[i][0] * 0.125f : -1e9f;
        o.y = valid ? acc[i][1] * 0.125f : -1e9f;
        o.z = valid ? acc[i][2] * 0.125f : -1e9f;
        o.w = valid ? acc[i][3] * 0.125f : -1e9f;
        *(float4*)(ob + (size_t)(ty * 4 + i) * 768 + tx * 4) = o;
    }
}

// ---------------- softmax over 768 keys ----------------
__global__ void lsoftmax_kernel(float* __restrict__ sc)
{
    float* r = sc + (size_t)blockIdx.x * 768;
    int t = threadIdx.x;
    float v0 = r[t], v1 = r[t + 256], v2 = r[t + 512];
    float m = fmaxf(v0, fmaxf(v1, v2));
    __shared__ float red[8], red2[8];
#pragma unroll
    for (int o = 16; o > 0; o >>= 1) m = fmaxf(m, __shfl_xor_sync(0xffffffffu, m, o));
    if ((t & 31) == 0) red[t >> 5] = m;
    __syncthreads();
    float bm = fmaxf(fmaxf(fmaxf(red[0], red[1]), fmaxf(red[2], red[3])),
                     fmaxf(fmaxf(red[4], red[5]), fmaxf(red[6], red[7])));
    float e0 = expf(v0 - bm), e1 = expf(v1 - bm), e2 = expf(v2 - bm);
    float s = e0 + e1 + e2;
#pragma unroll
    for (int o = 16; o > 0; o >>= 1) s += __shfl_xor_sync(0xffffffffu, s, o);
    if ((t & 31) == 0) red2[t >> 5] = s;
    __syncthreads();
    float bs = red2[0]+red2[1]+red2[2]+red2[3]+red2[4]+red2[5]+red2[6]+red2[7];
    float inv = 1.f / bs;
    r[t] = e0 * inv; r[t + 256] = e1 * inv; r[t + 512] = e2 * inv;
}

// ---------------- out_l = attn @ bv3 -> att ----------------
__global__ void __launch_bounds__(256) outl_kernel(
    const float* __restrict__ sc, const float* __restrict__ v, float* __restrict__ att)
{
    __shared__ __align__(16) float As[32][68];
    __shared__ __align__(16) float Vs[32][68];
    int bw = blockIdx.y; int bh = bw >> 5; int w = bw & 31;
    int b = bh >> 1, lh = bh & 1;
    int m0 = blockIdx.x * 64;
    int tid = threadIdx.x;
    int tx = tid & 15, ty = tid >> 4;
    float acc[4][4] = {};
    const float* sb = sc + ((size_t)bw * WINSZ + m0) * 768;
    const float* vb = v + (size_t)b * NN * DIMM + (GH + lh) * 64;
    for (int k0 = 0; k0 < 768; k0 += 32) {
#pragma unroll
        for (int i = 0; i < 2; i++) {
            int s1 = tid + i * 256;
            {
                int r = s1 >> 3, c4 = (s1 & 7) * 4;
                float4 a = *(const float4*)(sb + (size_t)r * 768 + k0 + c4);
                As[c4+0][r] = a.x; As[c4+1][r] = a.y; As[c4+2][r] = a.z; As[c4+3][r] = a.w;
            }
            {
                int kr = s1 >> 4, c4 = (s1 & 15) * 4;
                int kn = (w - 1) * WINSZ + k0 + kr;
                float4 vv = make_float4(0.f, 0.f, 0.f, 0.f);
                if ((unsigned)kn < (unsigned)NN)
                    vv = *(const float4*)(vb + (size_t)kn * DIMM + c4);
                *(float4*)&Vs[kr][c4] = vv;
            }
        }
        __syncthreads();
#pragma unroll
        for (int kk = 0; kk < 32; kk++) {
            float4 a  = *(const float4*)&As[kk][ty*4];
            float4 bv = *(const float4*)&Vs[kk][tx*4];
            float av[4] = {a.x,a.y,a.z,a.w}, bb[4] = {bv.x,bv.y,bv.z,bv.w};
#pragma unroll
            for (int i = 0; i < 4; i++)
#pragma unroll
                for (int j = 0; j < 4; j++) acc[i][j] += av[i] * bb[j];
        }
        __syncthreads();
    }
#pragma unroll
    for (int i = 0; i < 4; i++) {
        int n = w * WINSZ + m0 + ty * 4 + i;
        float4 o = {acc[i][0], acc[i][1], acc[i][2], acc[i][3]};
        *(float4*)(att + ((size_t)b * NN + n) * DIMM + (GH + lh) * 64 + tx * 4) = o;
    }
}

// ---------------- launcher ----------------
extern "C" void kernel_launch(void* const* d_in, const int* in_sizes, int n_in,
                              void* d_out, int out_size)
{
    (void)in_sizes; (void)n_in; (void)out_size;
    const float* x    = (const float*)d_in[0];
    const float* Wq   = (const float*)d_in[1];
    const float* Wk   = (const float*)d_in[2];
    const float* Wv   = (const float*)d_in[3];
    const float* Wo   = (const float*)d_in[4];
    const float* bo   = (const float*)d_in[5];
    const float* proj = (const float*)d_in[6];
    float* out = (float*)d_out;

    float *q, *k, *v, *qp, *kp, *kmp, *km, *part, *ctx, *dinv, *att, *sc, *rq, *rk;
    cudaGetSymbolAddress((void**)&q, g_q);
    cudaGetSymbolAddress((void**)&k, g_k);
    cudaGetSymbolAddress((void**)&v, g_v);
    cudaGetSymbolAddress((void**)&qp, g_qp);
    cudaGetSymbolAddress((void**)&kp, g_kp);
    cudaGetSymbolAddress((void**)&kmp, g_kmaxp);
    cudaGetSymbolAddress((void**)&km, g_kmax);
    cudaGetSymbolAddress((void**)&part, g_part);
    cudaGetSymbolAddress((void**)&ctx, g_ctx);
    cudaGetSymbolAddress((void**)&dinv, g_dinv);
    cudaGetSymbolAddress((void**)&att, g_att);
    cudaGetSymbolAddress((void**)&sc, g_sc);
    cudaGetSymbolAddress((void**)&rq, g_rq);
    cudaGetSymbolAddress((void**)&rk, g_rk);

    const int M = BB * NN; // 16384
    dim3 gg(DIMM / 128, M / 128);
    sgemm128<<<gg, 256>>>(x, Wq, nullptr, q, M, DIMM, DIMM);
    sgemm128<<<gg, 256>>>(x, Wk, nullptr, k, M, DIMM, DIMM);
    sgemm128<<<gg, 256>>>(x, Wv, nullptr, v, M, DIMM, DIMM);

    dim3 gdd(NBF / 64, NN / 64, BHG);
    dd_kernel<<<gdd, 256>>>(q, proj, qp);
    dd_kernel<<<gdd, 256>>>(k, proj, kp);

    kmax_part_kernel<<<dim3(64, BHG), 256>>>(kp, kmp);
    kmax_final_kernel<<<BHG, 64>>>(kmp, km);

    qexp_kernel<<<BHG * NN / 8, 256>>>(q, qp);
    kexp_kernel<<<BHG * NN / 8, 256>>>(k, km, kp);

    ctx_partial_kernel<<<dim3(BHG, NSPLIT), 256>>>(kp, v, part);
    ctx_reduce_kernel<<<(BHG * 256 * 65 + 255) / 256, 256>>>(part, ctx);

    denom_kernel<<<BHG * NN / 8, 256>>>(qp, ctx, dinv);
    outg_kernel<<<dim3(NN / 64, BHG), 256>>>(qp, ctx, dinv, att);

    rope_kernel<<<BHL * NN * 32 / 256, 256>>>(q, k, rq, rk);
    lscore_kernel<<<dim3(12, 4, BHL * NWIN), 256>>>(rq, rk, sc);
    lsoftmax_kernel<<<BHL * NWIN * WINSZ, 256>>>(sc);
    outl_kernel<<<dim3(4, BHL * NWIN), 256>>>(sc, v, att);

    sgemm128<<<gg, 256>>>(att, Wo, bo, out, M, DIMM, DIMM);
}